// round 1
// baseline (speedup 1.0000x reference)
#include <cuda_runtime.h>

#define B_ 8
#define C_ 64
#define H_ 256
#define W_ 256
#define E_ 256
#define NH_ 8
#define HD_ 32
#define NPIX (H_*W_)

#define XS_STRIDE 257
// smem: xs[64*257] | wc2[64*16] | la[8*256] | srow[8] | sbv[8]
#define SMEM_FLOATS (64*XS_STRIDE + 64*16 + 8*256 + 16)

// scratch (no cudaMalloc allowed)
__device__ float g_wa[B_*NH_*C_];
__device__ float g_wb[B_*NH_*C_];
__device__ float g_wc[B_*NH_*C_];
__device__ float g_s [B_*NH_*3];
__device__ float g_part[(size_t)B_*H_*NH_*68];   // per (b,row,h): S[64], m, T, PJ, pad

#define FMA2(a, x, w) asm("fma.rn.f32x2 %0, %1, %2, %0;" : "+l"(a) : "l"(x), "l"(w))

// ---------------------------------------------------------------------------
// Prep: per (b,h) build wa/wb/wc[64] and scalars sa/sb/sc.
// logit[b,n,h] = sum_c x[b,c,n]*(xx*wa+yy*wb+wc)[c] + xx*sa+yy*sb+sc
// ---------------------------------------------------------------------------
__global__ void prep_kernel(const float* __restrict__ z,  const float* __restrict__ pos,
                            const float* __restrict__ Wq, const float* __restrict__ bq,
                            const float* __restrict__ Wk, const float* __restrict__ bk,
                            const float* __restrict__ Wp, const float* __restrict__ bp)
{
    int b = blockIdx.x >> 3, h = blockIdx.x & 7;
    __shared__ float tA[HD_], tB[HD_], tC[HD_];
    int tid = threadIdx.x;
    const float s = rsqrtf((float)HD_);
    if (tid < HD_) {
        int d = tid, e = h*HD_ + d;
        float qv = bq[e];
        const float* zr = z  + b*C_;
        const float* wq = Wq + e*C_;
        #pragma unroll 8
        for (int c = 0; c < C_; c++) qv += zr[c]*wq[c];
        float wp0 = Wp[2*d], wp1 = Wp[2*d+1];
        float p0 = pos[(b*NH_+h)*2], p1 = pos[(b*NH_+h)*2+1];
        float cc = bp[d] - wp0*p0 - wp1*p1;
        tA[d] = qv*wp0*s; tB[d] = qv*wp1*s; tC[d] = qv*cc*s;
    }
    __syncthreads();
    int c = tid;  // 64 threads
    float a = 0.f, bb = 0.f, cc = 0.f;
    #pragma unroll 8
    for (int d = 0; d < HD_; d++) {
        float w = Wk[(h*HD_+d)*C_ + c];
        a += tA[d]*w; bb += tB[d]*w; cc += tC[d]*w;
    }
    int base = (b*NH_+h)*C_;
    g_wa[base+c] = a; g_wb[base+c] = bb; g_wc[base+c] = cc;
    if (tid < 3) {
        const float* t = (tid==0) ? tA : ((tid==1) ? tB : tC);
        float sv = 0.f;
        for (int d = 0; d < HD_; d++) sv += t[d]*bk[h*HD_+d];
        g_s[(b*NH_+h)*3 + tid] = sv;
    }
}

// ---------------------------------------------------------------------------
// Main: one block per (batch, image row). Stage x row-tile (64 ch x 256 px),
// compute per-pixel logits for 8 heads, row-local softmax partials, and
// weighted channel sums S[h][c].
// ---------------------------------------------------------------------------
__global__ void __launch_bounds__(256, 2) main_kernel(const float* __restrict__ x)
{
    extern __shared__ float sm[];
    float* xs   = sm;                    // [64][257]
    float* wc2  = sm + 64*XS_STRIDE;     // [64][16] interleaved (wr,wb) pairs per head
    float* la   = wc2 + 64*16;           // [8][256] logits -> attn weights
    float* srow = la + 8*256;            // [8]
    float* sbv  = srow + 8;              // [8]

    int row = blockIdx.x, b = blockIdx.y;
    int tid = threadIdx.x;

    // per-row combined weights: wr = wc + row*wa, paired with wb for f32x2
    if (tid < 64) {
        int c = tid;
        float rf = (float)row;
        #pragma unroll
        for (int h = 0; h < 8; h++) {
            int gi = (b*NH_+h)*C_ + c;
            wc2[c*16 + 2*h]     = g_wc[gi] + rf*g_wa[gi];
            wc2[c*16 + 2*h + 1] = g_wb[gi];
        }
    } else if (tid < 72) {
        int h = tid - 64;
        srow[h] = g_s[(b*NH_+h)*3+2] + (float)row*g_s[(b*NH_+h)*3+0];
        sbv[h]  = g_s[(b*NH_+h)*3+1];
    }

    // stage x tile: x[b, c, row, :] for all c  (coalesced float4 loads)
    const float4* xg = reinterpret_cast<const float4*>(x + (size_t)b*C_*NPIX + (size_t)row*W_);
    for (int idx = tid; idx < 64*64; idx += 256) {
        int c = idx >> 6, q = idx & 63;
        float4 v = xg[(size_t)c*(NPIX/4) + q];
        float* d = xs + c*XS_STRIDE + q*4;
        d[0] = v.x; d[1] = v.y; d[2] = v.z; d[3] = v.w;
    }
    __syncthreads();

    // ---- Phase A: logits. thread = pixel p; packed f32x2 FMAs over 64 channels.
    {
        int p = tid;
        unsigned long long acc[8];
        #pragma unroll
        for (int h = 0; h < 8; h++) acc[h] = 0ULL;  // (0.f, 0.f)
        const float* xp = xs + p;
        #pragma unroll 4
        for (int c = 0; c < 64; c++) {
            float xv = xp[c*XS_STRIDE];
            unsigned long long xx;
            asm("mov.b64 %0, {%1, %1};" : "=l"(xx) : "f"(xv));
            const ulonglong2* wp = reinterpret_cast<const ulonglong2*>(wc2 + c*16);
            ulonglong2 wA = wp[0], wB = wp[1];
            FMA2(acc[0], xx, wA.x);
            FMA2(acc[1], xx, wA.y);
            FMA2(acc[2], xx, wB.x);
            FMA2(acc[3], xx, wB.y);
            ulonglong2 wC = wp[2], wD = wp[3];
            FMA2(acc[4], xx, wC.x);
            FMA2(acc[5], xx, wC.y);
            FMA2(acc[6], xx, wD.x);
            FMA2(acc[7], xx, wD.y);
        }
        float jf = (float)p;
        #pragma unroll
        for (int h = 0; h < 8; h++) {
            float r, bb;
            asm("mov.b64 {%0, %1}, %2;" : "=f"(r), "=f"(bb) : "l"(acc[h]));
            la[h*256 + p] = (r + srow[h]) + jf*(bb + sbv[h]);
        }
    }
    __syncthreads();

    int warp = tid >> 5, lane = tid & 31;

    // ---- softmax partials per head (warp h owns row h of la)
    {
        int h = warp;
        float* lr = la + h*256;
        float m = -1e30f;
        #pragma unroll
        for (int k = 0; k < 8; k++) m = fmaxf(m, lr[lane + 32*k]);
        #pragma unroll
        for (int o = 16; o; o >>= 1) m = fmaxf(m, __shfl_xor_sync(0xffffffffu, m, o));
        float t = 0.f, pj = 0.f;
        #pragma unroll
        for (int k = 0; k < 8; k++) {
            int j = lane + 32*k;
            float e = __expf(lr[j] - m);
            lr[j] = e; t += e; pj += e*(float)j;
        }
        #pragma unroll
        for (int o = 16; o; o >>= 1) {
            t  += __shfl_xor_sync(0xffffffffu, t,  o);
            pj += __shfl_xor_sync(0xffffffffu, pj, o);
        }
        if (lane == 0) {
            float* pb = g_part + ((size_t)(b*H_+row)*NH_ + h)*68;
            pb[64] = m; pb[65] = t; pb[66] = pj;
        }
    }
    __syncthreads();

    // ---- Phase B: S[h][c] = sum_p attn[h][p]*x[c][p]. warp h, lane owns c=lane & lane+32.
    {
        int h = warp;
        const float* x0 = xs + lane*XS_STRIDE;
        const float* x1 = xs + (lane+32)*XS_STRIDE;
        const float4* ar = reinterpret_cast<const float4*>(la + h*256);
        float a0 = 0.f, a1 = 0.f;
        #pragma unroll 4
        for (int q = 0; q < 64; q++) {
            float4 av = ar[q];
            int p4 = q*4;
            a0 += av.x*x0[p4] + av.y*x0[p4+1] + av.z*x0[p4+2] + av.w*x0[p4+3];
            a1 += av.x*x1[p4] + av.y*x1[p4+1] + av.z*x1[p4+2] + av.w*x1[p4+3];
        }
        float* pb = g_part + ((size_t)(b*H_+row)*NH_ + h)*68;
        pb[lane]      = a0;
        pb[lane + 32] = a1;
    }
}

// ---------------------------------------------------------------------------
// Combine: per (b,h) rescale 256 row-partials, project values, emit outputs.
// out layout: values[8][8][256] then pos_out[8][8][2]
// ---------------------------------------------------------------------------
__global__ void combine_kernel(const float* __restrict__ Wv, const float* __restrict__ bv,
                               float* __restrict__ out)
{
    int b = blockIdx.x >> 3, h = blockIdx.x & 7;
    __shared__ float red[256], fsh[256], Ssh[64], Sp[4][64];
    __shared__ float Msh, Tsh, P0sh, P1sh;
    int tid = threadIdx.x;

    const float* pb = g_part + ((size_t)(b*H_+tid)*NH_ + h)*68;
    float m = pb[64];
    red[tid] = m; __syncthreads();
    for (int o = 128; o; o >>= 1) { if (tid < o) red[tid] = fmaxf(red[tid], red[tid+o]); __syncthreads(); }
    if (tid == 0) Msh = red[0];
    __syncthreads();
    float M = Msh;
    float f = __expf(m - M);
    fsh[tid] = f;
    float Tl = pb[65]*f;

    red[tid] = Tl; __syncthreads();
    for (int o = 128; o; o >>= 1) { if (tid < o) red[tid] += red[tid+o]; __syncthreads(); }
    if (tid == 0) Tsh = red[0];
    __syncthreads();

    red[tid] = Tl*(float)tid; __syncthreads();   // sum attn * row-index
    for (int o = 128; o; o >>= 1) { if (tid < o) red[tid] += red[tid+o]; __syncthreads(); }
    if (tid == 0) P0sh = red[0];
    __syncthreads();

    red[tid] = pb[66]*f; __syncthreads();        // sum attn * col-index
    for (int o = 128; o; o >>= 1) { if (tid < o) red[tid] += red[tid+o]; __syncthreads(); }
    if (tid == 0) P1sh = red[0];
    __syncthreads();

    // S[c] = sum_i f_i * S_i[c]
    int c = tid & 63, seg = tid >> 6;
    float sacc = 0.f;
    for (int i = seg*64; i < seg*64 + 64; i++) {
        const float* pi = g_part + ((size_t)(b*H_+i)*NH_ + h)*68;
        sacc += pi[c]*fsh[i];
    }
    Sp[seg][c] = sacc; __syncthreads();
    if (tid < 64) Ssh[tid] = (Sp[0][tid] + Sp[1][tid] + Sp[2][tid] + Sp[3][tid]) / Tsh;
    __syncthreads();

    // values[e] = bv[e] + Wv[e,:] . (S/T)
    int e = tid;
    float acc = bv[e];
    const float* wv = Wv + e*C_;
    #pragma unroll 8
    for (int c2 = 0; c2 < C_; c2++) acc += wv[c2]*Ssh[c2];
    out[(size_t)(b*NH_+h)*E_ + e] = acc;

    if (tid == 0) {
        float invT = 1.f/Tsh;
        out[B_*NH_*E_ + (b*NH_+h)*2]     = P0sh*invT;
        out[B_*NH_*E_ + (b*NH_+h)*2 + 1] = P1sh*invT;
    }
}

extern "C" void kernel_launch(void* const* d_in, const int* in_sizes, int n_in,
                              void* d_out, int out_size)
{
    const float* x   = (const float*)d_in[0];
    const float* z   = (const float*)d_in[1];
    const float* pos = (const float*)d_in[2];
    const float* Wq  = (const float*)d_in[3];
    const float* bq  = (const float*)d_in[4];
    const float* Wk  = (const float*)d_in[5];
    const float* bk  = (const float*)d_in[6];
    const float* Wv  = (const float*)d_in[7];
    const float* bv  = (const float*)d_in[8];
    const float* Wp  = (const float*)d_in[9];
    const float* bp  = (const float*)d_in[10];
    float* out = (float*)d_out;

    cudaFuncSetAttribute(main_kernel, cudaFuncAttributeMaxDynamicSharedMemorySize,
                         SMEM_FLOATS * (int)sizeof(float));

    prep_kernel<<<B_*NH_, 64>>>(z, pos, Wq, bq, Wk, bk, Wp, bp);
    main_kernel<<<dim3(H_, B_), 256, SMEM_FLOATS * sizeof(float)>>>(x);
    combine_kernel<<<B_*NH_, 256>>>(Wv, bv, out);
}

// round 2
// speedup vs baseline: 1.0625x; 1.0625x over previous
#include <cuda_runtime.h>

#define B_ 8
#define C_ 64
#define H_ 256
#define W_ 256
#define E_ 256
#define NH_ 8
#define HD_ 32
#define NPIX (H_*W_)

// shared layout (floats): xs[256*65] | la[256*12] | w8[64*16] | red[104] | srow[8] | sbv[8]
#define XS_F   (256*65)
#define LA_F   (256*12)
#define W8_F   (64*16)
#define RED_F  104
#define SMEM_FLOATS (XS_F + LA_F + W8_F + RED_F + 16)

__device__ float g_wa[B_*NH_*C_];
__device__ float g_wb[B_*NH_*C_];
__device__ float g_wc[B_*NH_*C_];
__device__ float g_s [B_*NH_*3];
__device__ float g_part[(size_t)B_*H_*NH_*68];   // per (b,row,h): S[64], m, T, PJ, pad

#define FMA2(a, x, w) asm("fma.rn.f32x2 %0, %1, %2, %0;" : "+l"(a) : "l"(x), "l"(w))

// ---------------------------------------------------------------------------
// Prep: per (b,h) build wa/wb/wc[64] and scalars sa/sb/sc.
// ---------------------------------------------------------------------------
__global__ void prep_kernel(const float* __restrict__ z,  const float* __restrict__ pos,
                            const float* __restrict__ Wq, const float* __restrict__ bq,
                            const float* __restrict__ Wk, const float* __restrict__ bk,
                            const float* __restrict__ Wp, const float* __restrict__ bp)
{
    int b = blockIdx.x >> 3, h = blockIdx.x & 7;
    __shared__ float tA[HD_], tB[HD_], tC[HD_];
    int tid = threadIdx.x;
    const float s = 0.1767766952966369f;  // 1/sqrt(32)

    // stage 1: qv[d] with 4 threads per d
    {
        int d = tid >> 2, q = tid & 3;
        int e = h*HD_ + d;
        const float* zr = z + b*C_;
        const float* wq = Wq + e*C_;
        float qv = 0.f;
        #pragma unroll
        for (int c = q*16; c < q*16+16; c++) qv += zr[c]*wq[c];
        qv += __shfl_xor_sync(0xffffffffu, qv, 1);
        qv += __shfl_xor_sync(0xffffffffu, qv, 2);
        if (q == 0) {
            qv += bq[e];
            float wp0 = Wp[2*d], wp1 = Wp[2*d+1];
            float p0 = pos[(b*NH_+h)*2], p1 = pos[(b*NH_+h)*2+1];
            float cc = bp[d] - wp0*p0 - wp1*p1;
            tA[d] = qv*wp0*s; tB[d] = qv*wp1*s; tC[d] = qv*cc*s;
        }
    }
    __syncthreads();
    // stage 2: project through Wk, 2 threads per c
    {
        int c = tid >> 1, half = tid & 1;
        const float* wkb = Wk + h*HD_*C_ + c;
        float a = 0.f, bb = 0.f, cc = 0.f;
        #pragma unroll
        for (int d = half*16; d < half*16+16; d++) {
            float w = wkb[d*C_];
            a += tA[d]*w; bb += tB[d]*w; cc += tC[d]*w;
        }
        a  += __shfl_xor_sync(0xffffffffu, a, 1);
        bb += __shfl_xor_sync(0xffffffffu, bb, 1);
        cc += __shfl_xor_sync(0xffffffffu, cc, 1);
        if (half == 0) {
            int base = (b*NH_+h)*C_;
            g_wa[base+c] = a; g_wb[base+c] = bb; g_wc[base+c] = cc;
        }
    }
    if (tid < 3) {
        const float* t = (tid==0) ? tA : ((tid==1) ? tB : tC);
        float sv = 0.f;
        #pragma unroll
        for (int d = 0; d < HD_; d++) sv += t[d]*bk[h*HD_+d];
        g_s[(b*NH_+h)*3 + tid] = sv;
    }
}

// ---------------------------------------------------------------------------
// Main: one block per (b, row). 128 threads, 2 pixels/thread in phase A.
// xs pixel-major [256][65]; attn pixel-major [256][12].
// ---------------------------------------------------------------------------
__global__ void __launch_bounds__(128, 2) main_kernel(const float* __restrict__ x)
{
    extern __shared__ float sm[];
    float* xs   = sm;                      // [256][65]
    float* la   = sm + XS_F;               // [256][12]
    float* w8   = la + LA_F;               // [64][16] (wr,wb) pairs per head; reused as Sp in phase B
    float* red  = w8 + W8_F;               // red_m[32] red_t[32] red_pj[32] mfin[8]
    float* srow = red + RED_F;             // [8]
    float* sbv  = srow + 8;                // [8]
    float* red_m = red, *red_t = red + 32, *red_pj = red + 64, *mfin = red + 96;

    int row = blockIdx.x, b = blockIdx.y;
    int tid = threadIdx.x;
    int warp = tid >> 5, lane = tid & 31;

    // per-row combined weights
    if (tid < 64) {
        int c = tid;
        float rf = (float)row;
        #pragma unroll
        for (int h = 0; h < 8; h++) {
            int gi = (b*NH_+h)*C_ + c;
            w8[c*16 + 2*h]     = g_wc[gi] + rf*g_wa[gi];
            w8[c*16 + 2*h + 1] = g_wb[gi];
        }
    } else if (tid < 72) {
        int h = tid - 64;
        srow[h] = g_s[(b*NH_+h)*3+2] + (float)row*g_s[(b*NH_+h)*3+0];
        sbv[h]  = g_s[(b*NH_+h)*3+1];
    }

    // stage x tile transposed: xs[p][c] (scalar LDG coalesced, scalar STS conflict-free)
    {
        const float* xg = x + (size_t)b*C_*NPIX + (size_t)row*W_;
        #pragma unroll 8
        for (int idx = tid; idx < C_*W_; idx += 128) {
            int c = idx >> 8, p = idx & 255;
            xs[p*65 + c] = __ldg(xg + (size_t)c*NPIX + p);
        }
    }
    __syncthreads();

    // ---- Phase A: logits, 2 pixels per thread (cols tid, tid+128)
    int col0 = tid, col1 = tid + 128;
    float l0[8], l1[8];
    {
        unsigned long long acc0[8], acc1[8];
        #pragma unroll
        for (int h = 0; h < 8; h++) { acc0[h] = 0ULL; acc1[h] = 0ULL; }
        const float* xr0 = xs + col0*65;
        const float* xr1 = xs + col1*65;
        #pragma unroll 4
        for (int c = 0; c < 64; c++) {
            float x0 = xr0[c], x1 = xr1[c];
            unsigned long long xx0, xx1;
            asm("mov.b64 %0, {%1, %1};" : "=l"(xx0) : "f"(x0));
            asm("mov.b64 %0, {%1, %1};" : "=l"(xx1) : "f"(x1));
            const ulonglong2* wp = reinterpret_cast<const ulonglong2*>(w8 + c*16);
            ulonglong2 wA = wp[0], wB = wp[1];
            FMA2(acc0[0], xx0, wA.x);  FMA2(acc1[0], xx1, wA.x);
            FMA2(acc0[1], xx0, wA.y);  FMA2(acc1[1], xx1, wA.y);
            FMA2(acc0[2], xx0, wB.x);  FMA2(acc1[2], xx1, wB.x);
            FMA2(acc0[3], xx0, wB.y);  FMA2(acc1[3], xx1, wB.y);
            ulonglong2 wC = wp[2], wD = wp[3];
            FMA2(acc0[4], xx0, wC.x);  FMA2(acc1[4], xx1, wC.x);
            FMA2(acc0[5], xx0, wC.y);  FMA2(acc1[5], xx1, wC.y);
            FMA2(acc0[6], xx0, wD.x);  FMA2(acc1[6], xx1, wD.x);
            FMA2(acc0[7], xx0, wD.y);  FMA2(acc1[7], xx1, wD.y);
        }
        float c0f = (float)col0, c1f = (float)col1;
        #pragma unroll
        for (int h = 0; h < 8; h++) {
            float r, bb;
            asm("mov.b64 {%0, %1}, %2;" : "=f"(r), "=f"(bb) : "l"(acc0[h]));
            l0[h] = (r + srow[h]) + c0f*(bb + sbv[h]);
            asm("mov.b64 {%0, %1}, %2;" : "=f"(r), "=f"(bb) : "l"(acc1[h]));
            l1[h] = (r + srow[h]) + c1f*(bb + sbv[h]);
        }
    }

    // ---- softmax over the row (registers + shuffles)
    {
        float mh[8];
        #pragma unroll
        for (int h = 0; h < 8; h++) mh[h] = fmaxf(l0[h], l1[h]);
        #pragma unroll
        for (int o = 16; o; o >>= 1) {
            #pragma unroll
            for (int h = 0; h < 8; h++)
                mh[h] = fmaxf(mh[h], __shfl_xor_sync(0xffffffffu, mh[h], o));
        }
        if (lane == 0) {
            #pragma unroll
            for (int h = 0; h < 8; h++) red_m[warp*8 + h] = mh[h];
        }
        __syncthreads();
        if (tid < 8)
            mfin[tid] = fmaxf(fmaxf(red_m[tid], red_m[8+tid]),
                              fmaxf(red_m[16+tid], red_m[24+tid]));
        __syncthreads();

        float th[8], pjh[8];
        float c0f = (float)col0, c1f = (float)col1;
        float e0[8], e1[8];
        #pragma unroll
        for (int h = 0; h < 8; h++) {
            float M = mfin[h];
            e0[h] = __expf(l0[h] - M);
            e1[h] = __expf(l1[h] - M);
            th[h]  = e0[h] + e1[h];
            pjh[h] = e0[h]*c0f + e1[h]*c1f;
        }
        // store attn pixel-major
        *reinterpret_cast<float4*>(la + col0*12)     = make_float4(e0[0], e0[1], e0[2], e0[3]);
        *reinterpret_cast<float4*>(la + col0*12 + 4) = make_float4(e0[4], e0[5], e0[6], e0[7]);
        *reinterpret_cast<float4*>(la + col1*12)     = make_float4(e1[0], e1[1], e1[2], e1[3]);
        *reinterpret_cast<float4*>(la + col1*12 + 4) = make_float4(e1[4], e1[5], e1[6], e1[7]);

        #pragma unroll
        for (int o = 16; o; o >>= 1) {
            #pragma unroll
            for (int h = 0; h < 8; h++) {
                th[h]  += __shfl_xor_sync(0xffffffffu, th[h],  o);
                pjh[h] += __shfl_xor_sync(0xffffffffu, pjh[h], o);
            }
        }
        if (lane == 0) {
            #pragma unroll
            for (int h = 0; h < 8; h++) {
                red_t[warp*8 + h]  = th[h];
                red_pj[warp*8 + h] = pjh[h];
            }
        }
        __syncthreads();
        if (tid < 8) {
            float T  = red_t[tid]  + red_t[8+tid]  + red_t[16+tid]  + red_t[24+tid];
            float PJ = red_pj[tid] + red_pj[8+tid] + red_pj[16+tid] + red_pj[24+tid];
            size_t pb = ((size_t)(b*H_ + row)*NH_ + tid)*68;
            g_part[pb + 64] = mfin[tid];
            g_part[pb + 65] = T;
            g_part[pb + 66] = PJ;
        }
    }

    // ---- Phase B: S[h][c] = sum_p e[p][h]*x[p][c]
    {
        int c = tid & 63, g = tid >> 6;
        float sa[8];
        #pragma unroll
        for (int h = 0; h < 8; h++) sa[h] = 0.f;
        int pbase = g*128;
        #pragma unroll 4
        for (int i = 0; i < 128; i++) {
            int p = pbase + i;
            float xv = xs[p*65 + c];
            float4 ea = *reinterpret_cast<const float4*>(la + p*12);
            float4 eb = *reinterpret_cast<const float4*>(la + p*12 + 4);
            sa[0] += ea.x*xv; sa[1] += ea.y*xv; sa[2] += ea.z*xv; sa[3] += ea.w*xv;
            sa[4] += eb.x*xv; sa[5] += eb.y*xv; sa[6] += eb.z*xv; sa[7] += eb.w*xv;
        }
        float* Sp = w8;  // reuse (1024 floats = 128 threads * 8)
        __syncthreads();   // ensure all phase-A reads of w8 done (they are) & ordering
        *reinterpret_cast<float4*>(Sp + tid*8)     = make_float4(sa[0], sa[1], sa[2], sa[3]);
        *reinterpret_cast<float4*>(Sp + tid*8 + 4) = make_float4(sa[4], sa[5], sa[6], sa[7]);
        __syncthreads();
        if (tid < 64) {
            size_t chk = (size_t)(b*H_ + row)*NH_;
            #pragma unroll
            for (int h = 0; h < 8; h++)
                g_part[(chk + h)*68 + tid] = Sp[tid*8 + h] + Sp[(tid+64)*8 + h];
        }
    }
}

// ---------------------------------------------------------------------------
// Combine: per (b,h) rescale 256 row-partials, project values, emit outputs.
// ---------------------------------------------------------------------------
__global__ void combine_kernel(const float* __restrict__ Wv, const float* __restrict__ bv,
                               float* __restrict__ out)
{
    int b = blockIdx.x >> 3, h = blockIdx.x & 7;
    __shared__ float red[256], fsh[256], Ssh[64], Sp[4][64];
    __shared__ float Msh, Tsh, P0sh, P1sh;
    int tid = threadIdx.x;

    const float* pb = g_part + ((size_t)(b*H_+tid)*NH_ + h)*68;
    float m = pb[64];
    red[tid] = m; __syncthreads();
    for (int o = 128; o; o >>= 1) { if (tid < o) red[tid] = fmaxf(red[tid], red[tid+o]); __syncthreads(); }
    if (tid == 0) Msh = red[0];
    __syncthreads();
    float M = Msh;
    float f = __expf(m - M);
    fsh[tid] = f;
    float Tl = pb[65]*f;

    red[tid] = Tl; __syncthreads();
    for (int o = 128; o; o >>= 1) { if (tid < o) red[tid] += red[tid+o]; __syncthreads(); }
    if (tid == 0) Tsh = red[0];
    __syncthreads();

    red[tid] = Tl*(float)tid; __syncthreads();
    for (int o = 128; o; o >>= 1) { if (tid < o) red[tid] += red[tid+o]; __syncthreads(); }
    if (tid == 0) P0sh = red[0];
    __syncthreads();

    red[tid] = pb[66]*f; __syncthreads();
    for (int o = 128; o; o >>= 1) { if (tid < o) red[tid] += red[tid+o]; __syncthreads(); }
    if (tid == 0) P1sh = red[0];
    __syncthreads();

    int c = tid & 63, seg = tid >> 6;
    float sacc = 0.f;
    for (int i = seg*64; i < seg*64 + 64; i++) {
        const float* pi = g_part + ((size_t)(b*H_+i)*NH_ + h)*68;
        sacc += pi[c]*fsh[i];
    }
    Sp[seg][c] = sacc; __syncthreads();
    if (tid < 64) Ssh[tid] = (Sp[0][tid] + Sp[1][tid] + Sp[2][tid] + Sp[3][tid]) / Tsh;
    __syncthreads();

    int e = tid;
    float acc = bv[e];
    const float* wv = Wv + e*C_;
    #pragma unroll 8
    for (int c2 = 0; c2 < C_; c2++) acc += wv[c2]*Ssh[c2];
    out[(size_t)(b*NH_+h)*E_ + e] = acc;

    if (tid == 0) {
        float invT = 1.f/Tsh;
        out[B_*NH_*E_ + (b*NH_+h)*2]     = P0sh*invT;
        out[B_*NH_*E_ + (b*NH_+h)*2 + 1] = P1sh*invT;
    }
}

extern "C" void kernel_launch(void* const* d_in, const int* in_sizes, int n_in,
                              void* d_out, int out_size)
{
    const float* x   = (const float*)d_in[0];
    const float* z   = (const float*)d_in[1];
    const float* pos = (const float*)d_in[2];
    const float* Wq  = (const float*)d_in[3];
    const float* bq  = (const float*)d_in[4];
    const float* Wk  = (const float*)d_in[5];
    const float* bk  = (const float*)d_in[6];
    const float* Wv  = (const float*)d_in[7];
    const float* bv  = (const float*)d_in[8];
    const float* Wp  = (const float*)d_in[9];
    const float* bp  = (const float*)d_in[10];
    float* out = (float*)d_out;

    cudaFuncSetAttribute(main_kernel, cudaFuncAttributeMaxDynamicSharedMemorySize,
                         SMEM_FLOATS * (int)sizeof(float));

    prep_kernel<<<B_*NH_, 128>>>(z, pos, Wq, bq, Wk, bk, Wp, bp);
    main_kernel<<<dim3(H_, B_), 128, SMEM_FLOATS * sizeof(float)>>>(x);
    combine_kernel<<<B_*NH_, 256>>>(Wv, bv, out);
}

// round 4
// speedup vs baseline: 1.4987x; 1.4106x over previous
#include <cuda_runtime.h>

#define B_ 8
#define C_ 64
#define H_ 256
#define W_ 256
#define E_ 256
#define NH_ 8
#define HD_ 32
#define NPIX (H_*W_)

// shared layout (floats): xs[256*65] | la[256*12] | w8[64*16] | red[104] | srow[8] | sbv[8]
#define XS_F   (256*65)
#define LA_F   (256*12)
#define W8_F   (64*16)
#define RED_F  104
#define SMEM_FLOATS (XS_F + LA_F + W8_F + RED_F + 16)

__device__ float g_wa[B_*NH_*C_];
__device__ float g_wb[B_*NH_*C_];
__device__ float g_wc[B_*NH_*C_];
__device__ float g_s [B_*NH_*3];
__device__ float g_part[(size_t)B_*H_*NH_*68];   // per (b,row,h): S[64], m, T, PJ, pad

#define FMA2(a, x, w) asm("fma.rn.f32x2 %0, %1, %2, %0;" : "+l"(a) : "l"(x), "l"(w))

// ---------------------------------------------------------------------------
// Prep: per (b,h) build wa/wb/wc[64] and scalars sa/sb/sc. 256 threads.
// ---------------------------------------------------------------------------
__global__ void prep_kernel(const float* __restrict__ z,  const float* __restrict__ pos,
                            const float* __restrict__ Wq, const float* __restrict__ bq,
                            const float* __restrict__ Wk, const float* __restrict__ bk,
                            const float* __restrict__ Wp, const float* __restrict__ bp)
{
    int b = blockIdx.x >> 3, h = blockIdx.x & 7;
    __shared__ float tA[HD_], tB[HD_], tC[HD_];
    int tid = threadIdx.x;
    const float s = 0.1767766952966369f;  // 1/sqrt(32)

    // stage 1: qv[d], 8 threads per d, float4 loads
    {
        int d = tid >> 3, q = tid & 7;
        int e = h*HD_ + d;
        const float4* zr = reinterpret_cast<const float4*>(z + b*C_);
        const float4* wq = reinterpret_cast<const float4*>(Wq + e*C_);
        float4 z0 = zr[q*2], z1 = zr[q*2+1];
        float4 w0 = __ldg(wq + q*2), w1 = __ldg(wq + q*2 + 1);
        float qv = z0.x*w0.x + z0.y*w0.y + z0.z*w0.z + z0.w*w0.w
                 + z1.x*w1.x + z1.y*w1.y + z1.z*w1.z + z1.w*w1.w;
        qv += __shfl_xor_sync(0xffffffffu, qv, 1);
        qv += __shfl_xor_sync(0xffffffffu, qv, 2);
        qv += __shfl_xor_sync(0xffffffffu, qv, 4);
        if (q == 0) {
            qv += bq[e];
            float wp0 = Wp[2*d], wp1 = Wp[2*d+1];
            float p0 = pos[(b*NH_+h)*2], p1 = pos[(b*NH_+h)*2+1];
            float cc = bp[d] - wp0*p0 - wp1*p1;
            tA[d] = qv*wp0*s; tB[d] = qv*wp1*s; tC[d] = qv*cc*s;
        }
    }
    __syncthreads();
    // stage 2: project through Wk, 4 threads per c
    {
        int c = tid >> 2, sub = tid & 3;
        const float* wkb = Wk + h*HD_*C_ + c;
        float a = 0.f, bb = 0.f, cc = 0.f;
        #pragma unroll
        for (int d = sub*8; d < sub*8+8; d++) {
            float w = __ldg(wkb + d*C_);
            a += tA[d]*w; bb += tB[d]*w; cc += tC[d]*w;
        }
        a  += __shfl_xor_sync(0xffffffffu, a, 1);
        bb += __shfl_xor_sync(0xffffffffu, bb, 1);
        cc += __shfl_xor_sync(0xffffffffu, cc, 1);
        a  += __shfl_xor_sync(0xffffffffu, a, 2);
        bb += __shfl_xor_sync(0xffffffffu, bb, 2);
        cc += __shfl_xor_sync(0xffffffffu, cc, 2);
        if (sub == 0) {
            int base = (b*NH_+h)*C_;
            g_wa[base+c] = a; g_wb[base+c] = bb; g_wc[base+c] = cc;
        }
    }
    if (tid < 3) {
        const float* t = (tid==0) ? tA : ((tid==1) ? tB : tC);
        float sv = 0.f;
        #pragma unroll
        for (int d = 0; d < HD_; d++) sv += t[d]*bk[h*HD_+d];
        g_s[(b*NH_+h)*3 + tid] = sv;
    }
}

// ---------------------------------------------------------------------------
// Main: one block per (b, row). 128 threads, 2 pixels/thread in phase A.
// xs pixel-major [256][65]; attn pixel-major [256][12].
// Staging: batched float4 LDG (8 in flight) -> scalar STS scatter.
// ---------------------------------------------------------------------------
__global__ void __launch_bounds__(128, 2) main_kernel(const float* __restrict__ x)
{
    extern __shared__ float sm[];
    float* xs   = sm;                      // [256][65]
    float* la   = sm + XS_F;               // [256][12]
    float* w8   = la + LA_F;               // [64][16]; reused as Sp in phase B
    float* red  = w8 + W8_F;               // red_m[32] red_t[32] red_pj[32] mfin[8]
    float* srow = red + RED_F;             // [8]
    float* sbv  = srow + 8;                // [8]
    float* red_m = red, *red_t = red + 32, *red_pj = red + 64, *mfin = red + 96;

    int row = blockIdx.x, b = blockIdx.y;
    int tid = threadIdx.x;
    int warp = tid >> 5, lane = tid & 31;

    // stage x tile (pixel-major transpose) with deep-MLP float4 loads
    {
        const float* xg = x + (size_t)b*C_*NPIX + (size_t)row*W_;
        #pragma unroll
        for (int k = 0; k < 32; k += 8) {
            float4 v[8];
            #pragma unroll
            for (int j = 0; j < 8; j++) {
                int idx = tid + (k+j)*128;           // 0..4095
                int c = idx >> 6, q = idx & 63;
                v[j] = __ldg(reinterpret_cast<const float4*>(xg + (size_t)c*NPIX) + q);
            }
            #pragma unroll
            for (int j = 0; j < 8; j++) {
                int idx = tid + (k+j)*128;
                int c = idx >> 6, q = idx & 63;
                float* d = xs + (q*4)*65 + c;
                d[0] = v[j].x; d[65] = v[j].y; d[130] = v[j].z; d[195] = v[j].w;
            }
        }
    }

    // per-row combined weights (overlaps with staging loads above)
    if (tid < 64) {
        int c = tid;
        float rf = (float)row;
        #pragma unroll
        for (int h = 0; h < 8; h++) {
            int gi = (b*NH_+h)*C_ + c;
            w8[c*16 + 2*h]     = g_wc[gi] + rf*g_wa[gi];
            w8[c*16 + 2*h + 1] = g_wb[gi];
        }
    } else if (tid < 72) {
        int h = tid - 64;
        srow[h] = g_s[(b*NH_+h)*3+2] + (float)row*g_s[(b*NH_+h)*3+0];
        sbv[h]  = g_s[(b*NH_+h)*3+1];
    }
    __syncthreads();

    // ---- Phase A: logits, 2 pixels per thread (cols tid, tid+128)
    int col0 = tid, col1 = tid + 128;
    float l0[8], l1[8];
    {
        unsigned long long acc0[8], acc1[8];
        #pragma unroll
        for (int h = 0; h < 8; h++) { acc0[h] = 0ULL; acc1[h] = 0ULL; }
        const float* xr0 = xs + col0*65;
        const float* xr1 = xs + col1*65;
        #pragma unroll 4
        for (int c = 0; c < 64; c++) {
            float x0 = xr0[c], x1 = xr1[c];
            unsigned long long xx0, xx1;
            asm("mov.b64 %0, {%1, %1};" : "=l"(xx0) : "f"(x0));
            asm("mov.b64 %0, {%1, %1};" : "=l"(xx1) : "f"(x1));
            const ulonglong2* wp = reinterpret_cast<const ulonglong2*>(w8 + c*16);
            ulonglong2 wA = wp[0], wB = wp[1];
            FMA2(acc0[0], xx0, wA.x);  FMA2(acc1[0], xx1, wA.x);
            FMA2(acc0[1], xx0, wA.y);  FMA2(acc1[1], xx1, wA.y);
            FMA2(acc0[2], xx0, wB.x);  FMA2(acc1[2], xx1, wB.x);
            FMA2(acc0[3], xx0, wB.y);  FMA2(acc1[3], xx1, wB.y);
            ulonglong2 wC = wp[2], wD = wp[3];
            FMA2(acc0[4], xx0, wC.x);  FMA2(acc1[4], xx1, wC.x);
            FMA2(acc0[5], xx0, wC.y);  FMA2(acc1[5], xx1, wC.y);
            FMA2(acc0[6], xx0, wD.x);  FMA2(acc1[6], xx1, wD.x);
            FMA2(acc0[7], xx0, wD.y);  FMA2(acc1[7], xx1, wD.y);
        }
        float c0f = (float)col0, c1f = (float)col1;
        #pragma unroll
        for (int h = 0; h < 8; h++) {
            float r, bb;
            asm("mov.b64 {%0, %1}, %2;" : "=f"(r), "=f"(bb) : "l"(acc0[h]));
            l0[h] = (r + srow[h]) + c0f*(bb + sbv[h]);
            asm("mov.b64 {%0, %1}, %2;" : "=f"(r), "=f"(bb) : "l"(acc1[h]));
            l1[h] = (r + srow[h]) + c1f*(bb + sbv[h]);
        }
    }

    // ---- softmax over the row (registers + shuffles)
    {
        float mh[8];
        #pragma unroll
        for (int h = 0; h < 8; h++) mh[h] = fmaxf(l0[h], l1[h]);
        #pragma unroll
        for (int o = 16; o; o >>= 1) {
            #pragma unroll
            for (int h = 0; h < 8; h++)
                mh[h] = fmaxf(mh[h], __shfl_xor_sync(0xffffffffu, mh[h], o));
        }
        if (lane == 0) {
            #pragma unroll
            for (int h = 0; h < 8; h++) red_m[warp*8 + h] = mh[h];
        }
        __syncthreads();
        if (tid < 8)
            mfin[tid] = fmaxf(fmaxf(red_m[tid], red_m[8+tid]),
                              fmaxf(red_m[16+tid], red_m[24+tid]));
        __syncthreads();

        float th[8], pjh[8];
        float c0f = (float)col0, c1f = (float)col1;
        float e0[8], e1[8];
        #pragma unroll
        for (int h = 0; h < 8; h++) {
            float M = mfin[h];
            e0[h] = __expf(l0[h] - M);
            e1[h] = __expf(l1[h] - M);
            th[h]  = e0[h] + e1[h];
            pjh[h] = e0[h]*c0f + e1[h]*c1f;
        }
        *reinterpret_cast<float4*>(la + col0*12)     = make_float4(e0[0], e0[1], e0[2], e0[3]);
        *reinterpret_cast<float4*>(la + col0*12 + 4) = make_float4(e0[4], e0[5], e0[6], e0[7]);
        *reinterpret_cast<float4*>(la + col1*12)     = make_float4(e1[0], e1[1], e1[2], e1[3]);
        *reinterpret_cast<float4*>(la + col1*12 + 4) = make_float4(e1[4], e1[5], e1[6], e1[7]);

        #pragma unroll
        for (int o = 16; o; o >>= 1) {
            #pragma unroll
            for (int h = 0; h < 8; h++) {
                th[h]  += __shfl_xor_sync(0xffffffffu, th[h],  o);
                pjh[h] += __shfl_xor_sync(0xffffffffu, pjh[h], o);
            }
        }
        if (lane == 0) {
            #pragma unroll
            for (int h = 0; h < 8; h++) {
                red_t[warp*8 + h]  = th[h];
                red_pj[warp*8 + h] = pjh[h];
            }
        }
        __syncthreads();
        if (tid < 8) {
            float T  = red_t[tid]  + red_t[8+tid]  + red_t[16+tid]  + red_t[24+tid];
            float PJ = red_pj[tid] + red_pj[8+tid] + red_pj[16+tid] + red_pj[24+tid];
            size_t pb = ((size_t)(b*H_ + row)*NH_ + tid)*68;
            g_part[pb + 64] = mfin[tid];
            g_part[pb + 65] = T;
            g_part[pb + 66] = PJ;
        }
    }

    // ---- Phase B: S[h][c] = sum_p e[p][h]*x[p][c]
    {
        int c = tid & 63, g = tid >> 6;
        float sa[8];
        #pragma unroll
        for (int h = 0; h < 8; h++) sa[h] = 0.f;
        int pbase = g*128;
        #pragma unroll 4
        for (int i = 0; i < 128; i++) {
            int p = pbase + i;
            float xv = xs[p*65 + c];
            float4 ea = *reinterpret_cast<const float4*>(la + p*12);
            float4 eb = *reinterpret_cast<const float4*>(la + p*12 + 4);
            sa[0] += ea.x*xv; sa[1] += ea.y*xv; sa[2] += ea.z*xv; sa[3] += ea.w*xv;
            sa[4] += eb.x*xv; sa[5] += eb.y*xv; sa[6] += eb.z*xv; sa[7] += eb.w*xv;
        }
        float* Sp = w8;  // reuse
        __syncthreads();
        *reinterpret_cast<float4*>(Sp + tid*8)     = make_float4(sa[0], sa[1], sa[2], sa[3]);
        *reinterpret_cast<float4*>(Sp + tid*8 + 4) = make_float4(sa[4], sa[5], sa[6], sa[7]);
        __syncthreads();
        if (tid < 64) {
            size_t chk = (size_t)(b*H_ + row)*NH_;
            #pragma unroll
            for (int h = 0; h < 8; h++)
                g_part[(chk + h)*68 + tid] = Sp[tid*8 + h] + Sp[(tid+64)*8 + h];
        }
    }
}

// ---------------------------------------------------------------------------
// Combine: per (b,h) rescale 256 row-partials, project values, emit outputs.
// Warp-shuffle reductions; unrolled L2 accumulation.
// ---------------------------------------------------------------------------
__global__ void combine_kernel(const float* __restrict__ Wv, const float* __restrict__ bv,
                               float* __restrict__ out)
{
    int b = blockIdx.x >> 3, h = blockIdx.x & 7;
    __shared__ float fsh[256], Ssh[64], Sp[4][64];
    __shared__ float wred[8], wsum[8][3];
    __shared__ float Msh;
    int tid = threadIdx.x, warp = tid >> 5, lane = tid & 31;

    const float* pb = g_part + ((size_t)(b*H_+tid)*NH_ + h)*68;
    float m = pb[64], T0 = pb[65], PJ0 = pb[66];

    // block max(m)
    float mm = m;
    #pragma unroll
    for (int o = 16; o; o >>= 1) mm = fmaxf(mm, __shfl_xor_sync(0xffffffffu, mm, o));
    if (lane == 0) wred[warp] = mm;
    __syncthreads();
    if (tid == 0) {
        float M = wred[0];
        #pragma unroll
        for (int i = 1; i < 8; i++) M = fmaxf(M, wred[i]);
        Msh = M;
    }
    __syncthreads();
    float M = Msh;
    float f = __expf(m - M);
    fsh[tid] = f;
    float Tl = T0*f, P0 = Tl*(float)tid, P1 = PJ0*f;
    #pragma unroll
    for (int o = 16; o; o >>= 1) {
        Tl += __shfl_xor_sync(0xffffffffu, Tl, o);
        P0 += __shfl_xor_sync(0xffffffffu, P0, o);
        P1 += __shfl_xor_sync(0xffffffffu, P1, o);
    }
    if (lane == 0) { wsum[warp][0] = Tl; wsum[warp][1] = P0; wsum[warp][2] = P1; }
    __syncthreads();
    float Tsh = 0.f, P0sh = 0.f, P1sh = 0.f;
    #pragma unroll
    for (int i = 0; i < 8; i++) { Tsh += wsum[i][0]; P0sh += wsum[i][1]; P1sh += wsum[i][2]; }

    // S[c] = sum_i f_i * S_i[c]
    int c = tid & 63, seg = tid >> 6;
    float sacc = 0.f;
    const float* pbase = g_part + ((size_t)(b*H_ + seg*64)*NH_ + h)*68 + c;
    #pragma unroll 4
    for (int i = 0; i < 64; i++)
        sacc += pbase[(size_t)i*NH_*68] * fsh[seg*64 + i];
    Sp[seg][c] = sacc; __syncthreads();
    if (tid < 64) Ssh[tid] = (Sp[0][tid] + Sp[1][tid] + Sp[2][tid] + Sp[3][tid]) / Tsh;
    __syncthreads();

    int e = tid;
    float acc = bv[e];
    const float4* wv = reinterpret_cast<const float4*>(Wv + e*C_);
    const float4* ss = reinterpret_cast<const float4*>(Ssh);
    #pragma unroll
    for (int c2 = 0; c2 < 16; c2++) {
        float4 w = __ldg(wv + c2), sv = ss[c2];
        acc += w.x*sv.x + w.y*sv.y + w.z*sv.z + w.w*sv.w;
    }
    out[(size_t)(b*NH_+h)*E_ + e] = acc;

    if (tid == 0) {
        float invT = 1.f/Tsh;
        out[B_*NH_*E_ + (b*NH_+h)*2]     = P0sh*invT;
        out[B_*NH_*E_ + (b*NH_+h)*2 + 1] = P1sh*invT;
    }
}

extern "C" void kernel_launch(void* const* d_in, const int* in_sizes, int n_in,
                              void* d_out, int out_size)
{
    const float* x   = (const float*)d_in[0];
    const float* z   = (const float*)d_in[1];
    const float* pos = (const float*)d_in[2];
    const float* Wq  = (const float*)d_in[3];
    const float* bq  = (const float*)d_in[4];
    const float* Wk  = (const float*)d_in[5];
    const float* bk  = (const float*)d_in[6];
    const float* Wv  = (const float*)d_in[7];
    const float* bv  = (const float*)d_in[8];
    const float* Wp  = (const float*)d_in[9];
    const float* bp  = (const float*)d_in[10];
    float* out = (float*)d_out;

    cudaFuncSetAttribute(main_kernel, cudaFuncAttributeMaxDynamicSharedMemorySize,
                         SMEM_FLOATS * (int)sizeof(float));

    prep_kernel<<<B_*NH_, 256>>>(z, pos, Wq, bq, Wk, bk, Wp, bp);
    main_kernel<<<dim3(H_, B_), 128, SMEM_FLOATS * sizeof(float)>>>(x);
    combine_kernel<<<B_*NH_, 256>>>(Wv, bv, out);
}

// round 5
// speedup vs baseline: 1.6476x; 1.0994x over previous
#include <cuda_runtime.h>

#define B_ 8
#define C_ 64
#define H_ 256
#define W_ 256
#define E_ 256
#define NH_ 8
#define HD_ 32
#define NPIX (H_*W_)

// shared layout (floats): xs[256*64] | la[256*12] | w8[64*16] | red[104] | srow[8] | sbv[8]
#define XS_F   (256*64)
#define LA_F   (256*12)
#define W8_F   (64*16)
#define RED_F  104
#define SMEM_FLOATS (XS_F + LA_F + W8_F + RED_F + 16)

__device__ float g_wa[B_*NH_*C_];
__device__ float g_wb[B_*NH_*C_];
__device__ float g_wc[B_*NH_*C_];
__device__ float g_s [B_*NH_*3];
__device__ float g_part[(size_t)B_*H_*NH_*68];   // per (b,row,h): S[64], m, T, PJ, pad

#define FMA2(a, x, w) asm("fma.rn.f32x2 %0, %1, %2, %0;" : "+l"(a) : "l"(x), "l"(w))

// ---------------------------------------------------------------------------
// Prep: per (b,h) build wa/wb/wc[64] and scalars sa/sb/sc. 256 threads.
// ---------------------------------------------------------------------------
__global__ void prep_kernel(const float* __restrict__ z,  const float* __restrict__ pos,
                            const float* __restrict__ Wq, const float* __restrict__ bq,
                            const float* __restrict__ Wk, const float* __restrict__ bk,
                            const float* __restrict__ Wp, const float* __restrict__ bp)
{
    int b = blockIdx.x >> 3, h = blockIdx.x & 7;
    __shared__ float tA[HD_], tB[HD_], tC[HD_];
    int tid = threadIdx.x;
    const float s = 0.1767766952966369f;  // 1/sqrt(32)

    {
        int d = tid >> 3, q = tid & 7;
        int e = h*HD_ + d;
        const float4* zr = reinterpret_cast<const float4*>(z + b*C_);
        const float4* wq = reinterpret_cast<const float4*>(Wq + e*C_);
        float4 z0 = zr[q*2], z1 = zr[q*2+1];
        float4 w0 = __ldg(wq + q*2), w1 = __ldg(wq + q*2 + 1);
        float qv = z0.x*w0.x + z0.y*w0.y + z0.z*w0.z + z0.w*w0.w
                 + z1.x*w1.x + z1.y*w1.y + z1.z*w1.z + z1.w*w1.w;
        qv += __shfl_xor_sync(0xffffffffu, qv, 1);
        qv += __shfl_xor_sync(0xffffffffu, qv, 2);
        qv += __shfl_xor_sync(0xffffffffu, qv, 4);
        if (q == 0) {
            qv += bq[e];
            float wp0 = Wp[2*d], wp1 = Wp[2*d+1];
            float p0 = pos[(b*NH_+h)*2], p1 = pos[(b*NH_+h)*2+1];
            float cc = bp[d] - wp0*p0 - wp1*p1;
            tA[d] = qv*wp0*s; tB[d] = qv*wp1*s; tC[d] = qv*cc*s;
        }
    }
    __syncthreads();
    {
        int c = tid >> 2, sub = tid & 3;
        const float* wkb = Wk + h*HD_*C_ + c;
        float a = 0.f, bb = 0.f, cc = 0.f;
        #pragma unroll
        for (int d = sub*8; d < sub*8+8; d++) {
            float w = __ldg(wkb + d*C_);
            a += tA[d]*w; bb += tB[d]*w; cc += tC[d]*w;
        }
        a  += __shfl_xor_sync(0xffffffffu, a, 1);
        bb += __shfl_xor_sync(0xffffffffu, bb, 1);
        cc += __shfl_xor_sync(0xffffffffu, cc, 1);
        a  += __shfl_xor_sync(0xffffffffu, a, 2);
        bb += __shfl_xor_sync(0xffffffffu, bb, 2);
        cc += __shfl_xor_sync(0xffffffffu, cc, 2);
        if (sub == 0) {
            int base = (b*NH_+h)*C_;
            g_wa[base+c] = a; g_wb[base+c] = bb; g_wc[base+c] = cc;
        }
    }
    if (tid < 3) {
        const float* t = (tid==0) ? tA : ((tid==1) ? tB : tC);
        float sv = 0.f;
        #pragma unroll
        for (int d = 0; d < HD_; d++) sv += t[d]*bk[h*HD_+d];
        g_s[(b*NH_+h)*3 + tid] = sv;
    }
}

// ---------------------------------------------------------------------------
// Main: one block per (b, row). 128 threads.
// xs swizzled pixel-major: word(p,c) = p*64 + ((c + 8*(p&3) + (p>>2)) & 63)
//   -> conflict-free for staging stores, phase-A reads, phase-B reads.
// ---------------------------------------------------------------------------
__global__ void __launch_bounds__(128, 2) main_kernel(const float* __restrict__ x)
{
    extern __shared__ float sm[];
    float* xs   = sm;                      // [256*64] swizzled
    float* la   = sm + XS_F;               // [256][12]
    float* w8   = la + LA_F;               // [64][16]; reused as Sp in phase B
    float* red  = w8 + W8_F;
    float* srow = red + RED_F;
    float* sbv  = srow + 8;
    float* red_m = red, *red_t = red + 32, *red_pj = red + 64, *mfin = red + 96;

    int row = blockIdx.x, b = blockIdx.y;
    int tid = threadIdx.x;
    int warp = tid >> 5, lane = tid & 31;

    // stage x tile with deep-MLP float4 loads, swizzled scatter (conflict-free)
    {
        const float* xg = x + (size_t)b*C_*NPIX + (size_t)row*W_;
        #pragma unroll
        for (int half = 0; half < 2; half++) {
            float4 v[16];
            #pragma unroll
            for (int j = 0; j < 16; j++) {
                int idx = tid + (half*16 + j)*128;
                int c = idx >> 6, q = idx & 63;
                v[j] = __ldg(reinterpret_cast<const float4*>(xg + (size_t)c*NPIX) + q);
            }
            #pragma unroll
            for (int j = 0; j < 16; j++) {
                int idx = tid + (half*16 + j)*128;
                int c = idx >> 6, q = idx & 63;
                int p4 = q*4*64;
                xs[p4       + ((c + q     ) & 63)] = v[j].x;
                xs[p4 + 64  + ((c + q +  8) & 63)] = v[j].y;
                xs[p4 + 128 + ((c + q + 16) & 63)] = v[j].z;
                xs[p4 + 192 + ((c + q + 24) & 63)] = v[j].w;
            }
        }
    }

    // per-row combined weights
    if (tid < 64) {
        int c = tid;
        float rf = (float)row;
        #pragma unroll
        for (int h = 0; h < 8; h++) {
            int gi = (b*NH_+h)*C_ + c;
            w8[c*16 + 2*h]     = g_wc[gi] + rf*g_wa[gi];
            w8[c*16 + 2*h + 1] = g_wb[gi];
        }
    } else if (tid < 72) {
        int h = tid - 64;
        srow[h] = g_s[(b*NH_+h)*3+2] + (float)row*g_s[(b*NH_+h)*3+0];
        sbv[h]  = g_s[(b*NH_+h)*3+1];
    }
    __syncthreads();

    // ---- Phase A: logits, 2 pixels per thread (cols tid, tid+128)
    int col0 = tid, col1 = tid + 128;
    float l0[8], l1[8];
    {
        unsigned long long acc0[8], acc1[8];
        #pragma unroll
        for (int h = 0; h < 8; h++) { acc0[h] = 0ULL; acc1[h] = 0ULL; }
        const float* xr0 = xs + col0*64;
        const float* xr1 = xs + col1*64;
        int G0 = ((col0 & 3) << 3) + (col0 >> 2);
        int G1 = ((col1 & 3) << 3) + (col1 >> 2);
        #pragma unroll 4
        for (int c = 0; c < 64; c++) {
            float x0 = xr0[(c + G0) & 63];
            float x1 = xr1[(c + G1) & 63];
            unsigned long long xx0, xx1;
            asm("mov.b64 %0, {%1, %1};" : "=l"(xx0) : "f"(x0));
            asm("mov.b64 %0, {%1, %1};" : "=l"(xx1) : "f"(x1));
            const ulonglong2* wp = reinterpret_cast<const ulonglong2*>(w8 + c*16);
            ulonglong2 wA = wp[0], wB = wp[1];
            FMA2(acc0[0], xx0, wA.x);  FMA2(acc1[0], xx1, wA.x);
            FMA2(acc0[1], xx0, wA.y);  FMA2(acc1[1], xx1, wA.y);
            FMA2(acc0[2], xx0, wB.x);  FMA2(acc1[2], xx1, wB.x);
            FMA2(acc0[3], xx0, wB.y);  FMA2(acc1[3], xx1, wB.y);
            ulonglong2 wC = wp[2], wD = wp[3];
            FMA2(acc0[4], xx0, wC.x);  FMA2(acc1[4], xx1, wC.x);
            FMA2(acc0[5], xx0, wC.y);  FMA2(acc1[5], xx1, wC.y);
            FMA2(acc0[6], xx0, wD.x);  FMA2(acc1[6], xx1, wD.x);
            FMA2(acc0[7], xx0, wD.y);  FMA2(acc1[7], xx1, wD.y);
        }
        float c0f = (float)col0, c1f = (float)col1;
        #pragma unroll
        for (int h = 0; h < 8; h++) {
            float r, bb;
            asm("mov.b64 {%0, %1}, %2;" : "=f"(r), "=f"(bb) : "l"(acc0[h]));
            l0[h] = (r + srow[h]) + c0f*(bb + sbv[h]);
            asm("mov.b64 {%0, %1}, %2;" : "=f"(r), "=f"(bb) : "l"(acc1[h]));
            l1[h] = (r + srow[h]) + c1f*(bb + sbv[h]);
        }
    }

    // ---- softmax over the row (registers + shuffles)
    {
        float mh[8];
        #pragma unroll
        for (int h = 0; h < 8; h++) mh[h] = fmaxf(l0[h], l1[h]);
        #pragma unroll
        for (int o = 16; o; o >>= 1) {
            #pragma unroll
            for (int h = 0; h < 8; h++)
                mh[h] = fmaxf(mh[h], __shfl_xor_sync(0xffffffffu, mh[h], o));
        }
        if (lane == 0) {
            #pragma unroll
            for (int h = 0; h < 8; h++) red_m[warp*8 + h] = mh[h];
        }
        __syncthreads();
        if (tid < 8)
            mfin[tid] = fmaxf(fmaxf(red_m[tid], red_m[8+tid]),
                              fmaxf(red_m[16+tid], red_m[24+tid]));
        __syncthreads();

        float th[8], pjh[8];
        float c0f = (float)col0, c1f = (float)col1;
        float e0[8], e1[8];
        #pragma unroll
        for (int h = 0; h < 8; h++) {
            float M = mfin[h];
            e0[h] = __expf(l0[h] - M);
            e1[h] = __expf(l1[h] - M);
            th[h]  = e0[h] + e1[h];
            pjh[h] = e0[h]*c0f + e1[h]*c1f;
        }
        *reinterpret_cast<float4*>(la + col0*12)     = make_float4(e0[0], e0[1], e0[2], e0[3]);
        *reinterpret_cast<float4*>(la + col0*12 + 4) = make_float4(e0[4], e0[5], e0[6], e0[7]);
        *reinterpret_cast<float4*>(la + col1*12)     = make_float4(e1[0], e1[1], e1[2], e1[3]);
        *reinterpret_cast<float4*>(la + col1*12 + 4) = make_float4(e1[4], e1[5], e1[6], e1[7]);

        #pragma unroll
        for (int o = 16; o; o >>= 1) {
            #pragma unroll
            for (int h = 0; h < 8; h++) {
                th[h]  += __shfl_xor_sync(0xffffffffu, th[h],  o);
                pjh[h] += __shfl_xor_sync(0xffffffffu, pjh[h], o);
            }
        }
        if (lane == 0) {
            #pragma unroll
            for (int h = 0; h < 8; h++) {
                red_t[warp*8 + h]  = th[h];
                red_pj[warp*8 + h] = pjh[h];
            }
        }
        __syncthreads();
        if (tid < 8) {
            float T  = red_t[tid]  + red_t[8+tid]  + red_t[16+tid]  + red_t[24+tid];
            float PJ = red_pj[tid] + red_pj[8+tid] + red_pj[16+tid] + red_pj[24+tid];
            size_t pb = ((size_t)(b*H_ + row)*NH_ + tid)*68;
            g_part[pb + 64] = mfin[tid];
            g_part[pb + 65] = T;
            g_part[pb + 66] = PJ;
        }
    }

    // ---- Phase B: S[h][c] = sum_p e[p][h]*x[p][c], head-pairs via FMA2
    {
        int c = tid & 63, g = tid >> 6;
        unsigned long long acc[4];
        #pragma unroll
        for (int j = 0; j < 4; j++) acc[j] = 0ULL;
        int pbase = g*128;
        #pragma unroll 4
        for (int i = 0; i < 128; i++) {
            int p = pbase + i;
            int col = (c + ((p & 3) << 3) + (p >> 2)) & 63;
            float xv = xs[p*64 + col];
            unsigned long long xx;
            asm("mov.b64 %0, {%1, %1};" : "=l"(xx) : "f"(xv));
            ulonglong2 eA = *reinterpret_cast<const ulonglong2*>(la + p*12);
            ulonglong2 eB = *reinterpret_cast<const ulonglong2*>(la + p*12 + 4);
            FMA2(acc[0], xx, eA.x);
            FMA2(acc[1], xx, eA.y);
            FMA2(acc[2], xx, eB.x);
            FMA2(acc[3], xx, eB.y);
        }
        float* Sp = w8;  // reuse
        __syncthreads();
        *reinterpret_cast<ulonglong2*>(Sp + tid*8)     = make_ulonglong2(acc[0], acc[1]);
        *reinterpret_cast<ulonglong2*>(Sp + tid*8 + 4) = make_ulonglong2(acc[2], acc[3]);
        __syncthreads();
        if (tid < 64) {
            size_t chk = (size_t)(b*H_ + row)*NH_;
            #pragma unroll
            for (int h = 0; h < 8; h++)
                g_part[(chk + h)*68 + tid] = Sp[tid*8 + h] + Sp[(tid+64)*8 + h];
        }
    }
}

// ---------------------------------------------------------------------------
// Combine: per (b,h) rescale 256 row-partials, project values, emit outputs.
// ---------------------------------------------------------------------------
__global__ void combine_kernel(const float* __restrict__ Wv, const float* __restrict__ bv,
                               float* __restrict__ out)
{
    int b = blockIdx.x >> 3, h = blockIdx.x & 7;
    __shared__ float fsh[256], Ssh[64], Sp[4][64];
    __shared__ float wred[8], wsum[8][3];
    __shared__ float Msh;
    int tid = threadIdx.x, warp = tid >> 5, lane = tid & 31;

    const float* pb = g_part + ((size_t)(b*H_+tid)*NH_ + h)*68;
    float m = pb[64], T0 = pb[65], PJ0 = pb[66];

    float mm = m;
    #pragma unroll
    for (int o = 16; o; o >>= 1) mm = fmaxf(mm, __shfl_xor_sync(0xffffffffu, mm, o));
    if (lane == 0) wred[warp] = mm;
    __syncthreads();
    if (tid == 0) {
        float M = wred[0];
        #pragma unroll
        for (int i = 1; i < 8; i++) M = fmaxf(M, wred[i]);
        Msh = M;
    }
    __syncthreads();
    float M = Msh;
    float f = __expf(m - M);
    fsh[tid] = f;
    float Tl = T0*f, P0 = Tl*(float)tid, P1 = PJ0*f;
    #pragma unroll
    for (int o = 16; o; o >>= 1) {
        Tl += __shfl_xor_sync(0xffffffffu, Tl, o);
        P0 += __shfl_xor_sync(0xffffffffu, P0, o);
        P1 += __shfl_xor_sync(0xffffffffu, P1, o);
    }
    if (lane == 0) { wsum[warp][0] = Tl; wsum[warp][1] = P0; wsum[warp][2] = P1; }
    __syncthreads();
    float Tsh = 0.f, P0sh = 0.f, P1sh = 0.f;
    #pragma unroll
    for (int i = 0; i < 8; i++) { Tsh += wsum[i][0]; P0sh += wsum[i][1]; P1sh += wsum[i][2]; }

    int c = tid & 63, seg = tid >> 6;
    float sacc = 0.f;
    const float* pbase = g_part + ((size_t)(b*H_ + seg*64)*NH_ + h)*68 + c;
    #pragma unroll 4
    for (int i = 0; i < 64; i++)
        sacc += pbase[(size_t)i*NH_*68] * fsh[seg*64 + i];
    Sp[seg][c] = sacc; __syncthreads();
    if (tid < 64) Ssh[tid] = (Sp[0][tid] + Sp[1][tid] + Sp[2][tid] + Sp[3][tid]) / Tsh;
    __syncthreads();

    int e = tid;
    float acc = bv[e];
    const float4* wv = reinterpret_cast<const float4*>(Wv + e*C_);
    const float4* ss = reinterpret_cast<const float4*>(Ssh);
    #pragma unroll
    for (int c2 = 0; c2 < 16; c2++) {
        float4 w = __ldg(wv + c2), sv = ss[c2];
        acc += w.x*sv.x + w.y*sv.y + w.z*sv.z + w.w*sv.w;
    }
    out[(size_t)(b*NH_+h)*E_ + e] = acc;

    if (tid == 0) {
        float invT = 1.f/Tsh;
        out[B_*NH_*E_ + (b*NH_+h)*2]     = P0sh*invT;
        out[B_*NH_*E_ + (b*NH_+h)*2 + 1] = P1sh*invT;
    }
}

extern "C" void kernel_launch(void* const* d_in, const int* in_sizes, int n_in,
                              void* d_out, int out_size)
{
    const float* x   = (const float*)d_in[0];
    const float* z   = (const float*)d_in[1];
    const float* pos = (const float*)d_in[2];
    const float* Wq  = (const float*)d_in[3];
    const float* bq  = (const float*)d_in[4];
    const float* Wk  = (const float*)d_in[5];
    const float* bk  = (const float*)d_in[6];
    const float* Wv  = (const float*)d_in[7];
    const float* bv  = (const float*)d_in[8];
    const float* Wp  = (const float*)d_in[9];
    const float* bp  = (const float*)d_in[10];
    float* out = (float*)d_out;

    cudaFuncSetAttribute(main_kernel, cudaFuncAttributeMaxDynamicSharedMemorySize,
                         SMEM_FLOATS * (int)sizeof(float));

    prep_kernel<<<B_*NH_, 256>>>(z, pos, Wq, bq, Wk, bk, Wp, bp);
    main_kernel<<<dim3(H_, B_), 128, SMEM_FLOATS * sizeof(float)>>>(x);
    combine_kernel<<<B_*NH_, 256>>>(Wv, bv, out);
}